// round 6
// baseline (speedup 1.0000x reference)
#include <cuda_runtime.h>
#include <math.h>

#define N_ROWS 65536   // 8192 * 8
#define DIM    256
#define KCODES 1024
#define BM     128     // rows per CTA
#define BN     128     // codes per chunk
#define BK     32      // D panel width
#define NCHUNK (KCODES / BN)   // 8
#define NPANEL (DIM / BK)      // 8
#define NBLOCKS (N_ROWS / BM)  // 512

#define POS_INF __builtin_huge_valf()

__device__ float g_norm_e[KCODES];    // ||e_k||^2
__device__ float g_norm_x[N_ROWS];    // ||x_r||^2
__device__ float g_partial[NBLOCKS];

// ---------------------------------------------------------------------------
// Kernel 1a: ||e_k||^2 for all codes
// ---------------------------------------------------------------------------
__global__ void vq_norms_e_kernel(const float* __restrict__ emb) {
    int k = blockIdx.x * blockDim.x + threadIdx.x;
    if (k < KCODES) {
        const float4* e4 = (const float4*)(emb + (size_t)k * DIM);
        float s = 0.0f;
        #pragma unroll 8
        for (int q = 0; q < DIM / 4; q++) {
            float4 v = e4[q];
            s += v.x * v.x + v.y * v.y + v.z * v.z + v.w * v.w;
        }
        g_norm_e[k] = s;
    }
}

// ---------------------------------------------------------------------------
// Kernel 1b: ||x_r||^2 for all rows (one warp per row, coalesced)
// ---------------------------------------------------------------------------
__global__ void vq_norms_x_kernel(const float* __restrict__ lat) {
    int warp = (blockIdx.x * blockDim.x + threadIdx.x) >> 5;
    int lane = threadIdx.x & 31;
    if (warp < N_ROWS) {
        const float4* x4 = (const float4*)(lat + (size_t)warp * DIM);
        float s = 0.0f;
        #pragma unroll
        for (int q = 0; q < 2; q++) {
            float4 v = x4[lane + 32 * q];
            s += v.x * v.x + v.y * v.y + v.z * v.z + v.w * v.w;
        }
        #pragma unroll
        for (int off = 16; off >= 1; off >>= 1)
            s += __shfl_xor_sync(0xffffffffu, s, off);
        if (lane == 0) g_norm_x[warp] = s;
    }
}

// ---------------------------------------------------------------------------
// Kernel 2: fused GEMM + argmin + gather + per-block loss partial
// dist(r,k) = fl32( fl32(||x||^2 + ||e||^2) - 2*dot ) -- replicates the
// reference's fp32 rounding (grid ~ulp(256)); dot computed with two-stage
// accumulation (chains <=32) so our dot error << one grid cell.
// ---------------------------------------------------------------------------
__global__ void __launch_bounds__(256, 1)
vq_main_kernel(const float* __restrict__ lat,
               const float* __restrict__ emb,
               float* __restrict__ out) {
    __shared__ float Xs[BM][BK + 1];
    __shared__ float Es[BN][BK + 1];
    __shared__ float s_nx[BM];
    __shared__ float s_row_min[BM];
    __shared__ int   s_row_idx[BM];
    __shared__ float s_warpsum[8];

    const int tid = threadIdx.x;
    const int tx = tid & 15;         // code sub-index
    const int ty = tid >> 4;         // row sub-index
    const int r0 = blockIdx.x * BM;

    if (tid < BM) {
        s_row_min[tid] = POS_INF;
        s_row_idx[tid] = 0;
        s_nx[tid] = g_norm_x[r0 + tid];
    }

    for (int c = 0; c < NCHUNK; c++) {
        float acc_hi[8][8];
        #pragma unroll
        for (int i = 0; i < 8; i++)
            #pragma unroll
            for (int j = 0; j < 8; j++)
                acc_hi[i][j] = 0.0f;

        for (int p = 0; p < NPANEL; p++) {
            __syncthreads();   // protect Xs/Es from previous iteration's readers
            // load X panel [BM x BK] : 1024 float4, 4 per thread
            #pragma unroll
            for (int t = tid; t < BM * (BK / 4); t += 256) {
                int row = t >> 3;
                int q   = t & 7;
                float4 v = *(const float4*)(lat + (size_t)(r0 + row) * DIM + p * BK + q * 4);
                Xs[row][q * 4 + 0] = v.x;
                Xs[row][q * 4 + 1] = v.y;
                Xs[row][q * 4 + 2] = v.z;
                Xs[row][q * 4 + 3] = v.w;
            }
            // load E panel [BN x BK]
            #pragma unroll
            for (int t = tid; t < BN * (BK / 4); t += 256) {
                int row = t >> 3;
                int q   = t & 7;
                float4 v = *(const float4*)(emb + (size_t)(c * BN + row) * DIM + p * BK + q * 4);
                Es[row][q * 4 + 0] = v.x;
                Es[row][q * 4 + 1] = v.y;
                Es[row][q * 4 + 2] = v.z;
                Es[row][q * 4 + 3] = v.w;
            }
            __syncthreads();

            // panel accumulator (chain length 32)
            float acc[8][8];
            #pragma unroll
            for (int i = 0; i < 8; i++)
                #pragma unroll
                for (int j = 0; j < 8; j++)
                    acc[i][j] = 0.0f;

            #pragma unroll 4
            for (int k = 0; k < BK; k++) {
                float a[8], b[8];
                #pragma unroll
                for (int i = 0; i < 8; i++) a[i] = Xs[ty + 16 * i][k];
                #pragma unroll
                for (int j = 0; j < 8; j++) b[j] = Es[tx + 16 * j][k];
                #pragma unroll
                for (int i = 0; i < 8; i++)
                    #pragma unroll
                    for (int j = 0; j < 8; j++)
                        acc[i][j] = __fmaf_rn(a[i], b[j], acc[i][j]);
            }

            // fold panel into master accumulator (chain length 8)
            #pragma unroll
            for (int i = 0; i < 8; i++)
                #pragma unroll
                for (int j = 0; j < 8; j++)
                    acc_hi[i][j] = __fadd_rn(acc_hi[i][j], acc[i][j]);
        }

        // per-row chunk argmin with the reference's exact fp32 rounding
        #pragma unroll
        for (int i = 0; i < 8; i++) {
            int row = ty + 16 * i;
            float nx = s_nx[row];
            float bv = POS_INF;
            int   bi = 0;
            #pragma unroll
            for (int j = 0; j < 8; j++) {
                int col = c * BN + tx + 16 * j;
                float ne = __ldg(&g_norm_e[col]);
                // dist = fl( fl(nx + ne) - fl(2*dot) ), no contraction
                float s = __fsub_rn(__fadd_rn(nx, ne),
                                    __fmul_rn(2.0f, acc_hi[i][j]));
                if (s < bv) { bv = s; bi = col; }   // ascending col -> first-min
            }
            #pragma unroll
            for (int off = 8; off >= 1; off >>= 1) {
                float ov = __shfl_xor_sync(0xffffffffu, bv, off, 16);
                int   oi = __shfl_xor_sync(0xffffffffu, bi, off, 16);
                if (ov < bv || (ov == bv && oi < bi)) { bv = ov; bi = oi; }
            }
            if (tx == 0) {   // single writer per row; strict < keeps earliest chunk
                if (bv < s_row_min[row]) {
                    s_row_min[row] = bv;
                    s_row_idx[row] = bi;
                }
            }
        }
    }
    __syncthreads();

    // epilogue: gather winning code rows, write output, rescore exact loss
    float lsum = 0.0f;
    const float4* lat4 = (const float4*)lat;
    const float4* emb4 = (const float4*)emb;
    float4*       out4 = (float4*)out;
    #pragma unroll
    for (int t = tid; t < BM * (DIM / 4); t += 256) {
        int row = t >> 6;             // DIM/4 = 64
        int q   = t & 63;
        int code = s_row_idx[row];
        float4 e = emb4[(size_t)code * (DIM / 4) + q];
        float4 x = lat4[(size_t)(r0 + row) * (DIM / 4) + q];
        out4[(size_t)(r0 + row) * (DIM / 4) + q] = e;
        float dx = x.x - e.x, dy = x.y - e.y, dz = x.z - e.z, dw = x.w - e.w;
        lsum += dx * dx + dy * dy + dz * dz + dw * dw;
    }

    // deterministic block reduce
    #pragma unroll
    for (int off = 16; off >= 1; off >>= 1)
        lsum += __shfl_xor_sync(0xffffffffu, lsum, off);
    if ((tid & 31) == 0) s_warpsum[tid >> 5] = lsum;
    __syncthreads();
    if (tid == 0) {
        float tot = 0.0f;
        #pragma unroll
        for (int w = 0; w < 8; w++) tot += s_warpsum[w];
        g_partial[blockIdx.x] = tot;
    }
}

// ---------------------------------------------------------------------------
// Kernel 3: deterministic loss finalize
// ---------------------------------------------------------------------------
__global__ void vq_finalize_kernel(float* __restrict__ out, int out_size) {
    __shared__ float s_warp[16];
    int tid = threadIdx.x;                 // 512 threads, one partial each
    float v = g_partial[tid];
    #pragma unroll
    for (int off = 16; off >= 1; off >>= 1)
        v += __shfl_xor_sync(0xffffffffu, v, off);
    if ((tid & 31) == 0) s_warp[tid >> 5] = v;
    __syncthreads();
    if (tid == 0) {
        float tot = 0.0f;
        #pragma unroll
        for (int w = 0; w < 16; w++) tot += s_warp[w];
        float mse = tot / (float)((size_t)N_ROWS * DIM);
        float vq_loss = mse * 1.25f;       // embedding + BETA*commitment (equal values)
        if (out_size > N_ROWS * DIM) out[N_ROWS * DIM] = vq_loss;
    }
}

// ---------------------------------------------------------------------------
extern "C" void kernel_launch(void* const* d_in, const int* in_sizes, int n_in,
                              void* d_out, int out_size) {
    const float* lat = (const float*)d_in[0];   // latents [8192, 2048] fp32
    const float* emb = (const float*)d_in[1];   // embedding [1024, 256] fp32
    float* out = (float*)d_out;

    vq_norms_e_kernel<<<(KCODES + 255) / 256, 256>>>(emb);
    vq_norms_x_kernel<<<(N_ROWS * 32 + 255) / 256, 256>>>(lat);
    vq_main_kernel<<<NBLOCKS, 256>>>(lat, emb, out);
    vq_finalize_kernel<<<1, NBLOCKS>>>(out, out_size);
}

// round 11
// speedup vs baseline: 1.6752x; 1.6752x over previous
#include <cuda_runtime.h>
#include <cuda_bf16.h>
#include <stdint.h>
#include <math.h>

#define N_ROWS 65536
#define DIM    256
#define KCODES 1024
#define BM     128
#define NBLOCKS (N_ROWS / BM)   // 512
#define NCHUNK  8               // codes: 8 chunks of 128
#define NPANEL  4               // K: 4 panels of 64
#define POS_INF __builtin_huge_valf()
#define FLAG_EPS 8e-5f

// ---------------- device globals ----------------
__device__ float g_norm_e[KCODES];
__device__ float g_norm_x[N_ROWS];
__device__ float g_partial[NBLOCKS];
__device__ int   g_idx[N_ROWS];
__device__ int   g_flaglist[N_ROWS];
__device__ int   g_nflag;
// codebook bf16 limbs, row-major [1024][256]
__device__ __align__(16) __nv_bfloat16 g_eh[KCODES * DIM];
__device__ __align__(16) __nv_bfloat16 g_el[KCODES * DIM];

// ---------------- smem layout (main kernel) ----------------
#define XPITCH 528     // [128 rows][264 bf16] pad -> ldmatrix conflict-free
#define EPITCH 144     // [128 codes][72 bf16]
#define OFF_XH  0                       // 67584
#define OFF_XL  67584                   // 67584
#define OFF_EH  135168                  // 18432
#define OFF_EL  153600                  // 18432
#define OFF_NE  172032                  // 4096
#define OFF_NX  176128                  // 512
#define SMEM_BYTES 176640

__device__ __forceinline__ uint32_t smem_u32(const void* p) {
    uint32_t a;
    asm("{ .reg .u64 t; cvta.to.shared.u64 t, %1; cvt.u32.u64 %0, t; }" : "=r"(a) : "l"(p));
    return a;
}
__device__ __forceinline__ void ldm_x4(uint32_t& r0, uint32_t& r1, uint32_t& r2, uint32_t& r3,
                                       uint32_t addr) {
    asm volatile("ldmatrix.sync.aligned.m8n8.x4.shared.b16 {%0,%1,%2,%3}, [%4];"
                 : "=r"(r0), "=r"(r1), "=r"(r2), "=r"(r3) : "r"(addr));
}
__device__ __forceinline__ void mma16816(float* c, uint32_t a0, uint32_t a1, uint32_t a2,
                                         uint32_t a3, uint32_t b0, uint32_t b1) {
    asm volatile("mma.sync.aligned.m16n8k16.row.col.f32.bf16.bf16.f32 "
                 "{%0,%1,%2,%3}, {%4,%5,%6,%7}, {%8,%9}, {%0,%1,%2,%3};"
                 : "+f"(c[0]), "+f"(c[1]), "+f"(c[2]), "+f"(c[3])
                 : "r"(a0), "r"(a1), "r"(a2), "r"(a3), "r"(b0), "r"(b1));
}
__device__ __forceinline__ uint32_t pack2(__nv_bfloat16 a, __nv_bfloat16 b) {
    __nv_bfloat162 p = __halves2bfloat162(a, b);
    return reinterpret_cast<uint32_t&>(p);
}
__device__ __forceinline__ void split2(float x, __nv_bfloat16& h, __nv_bfloat16& l) {
    h = __float2bfloat16(x);
    l = __float2bfloat16(__fsub_rn(x, __bfloat162float(h)));
}

// ---------------------------------------------------------------------------
// Kernel 1a: ||e_k||^2 + flag-counter reset
// ---------------------------------------------------------------------------
__global__ void vq_norms_e_kernel(const float* __restrict__ emb) {
    if (blockIdx.x == 0 && threadIdx.x == 0) g_nflag = 0;
    int k = blockIdx.x * blockDim.x + threadIdx.x;
    if (k < KCODES) {
        const float4* e4 = (const float4*)(emb + (size_t)k * DIM);
        float s = 0.0f;
        #pragma unroll 8
        for (int q = 0; q < DIM / 4; q++) {
            float4 v = e4[q];
            s += v.x * v.x + v.y * v.y + v.z * v.z + v.w * v.w;
        }
        g_norm_e[k] = s;
    }
}
// ---------------------------------------------------------------------------
// Kernel 1b: ||x_r||^2  (bit-identical to passing version)
// ---------------------------------------------------------------------------
__global__ void vq_norms_x_kernel(const float* __restrict__ lat) {
    int warp = (blockIdx.x * blockDim.x + threadIdx.x) >> 5;
    int lane = threadIdx.x & 31;
    if (warp < N_ROWS) {
        const float4* x4 = (const float4*)(lat + (size_t)warp * DIM);
        float s = 0.0f;
        #pragma unroll
        for (int q = 0; q < 2; q++) {
            float4 v = x4[lane + 32 * q];
            s += v.x * v.x + v.y * v.y + v.z * v.z + v.w * v.w;
        }
        #pragma unroll
        for (int off = 16; off >= 1; off >>= 1)
            s += __shfl_xor_sync(0xffffffffu, s, off);
        if (lane == 0) g_norm_x[warp] = s;
    }
}
// ---------------------------------------------------------------------------
// Kernel 1c: codebook -> bf16 limbs, row-major
// ---------------------------------------------------------------------------
__global__ void vq_convert_e_kernel(const float* __restrict__ emb) {
    int t = blockIdx.x * blockDim.x + threadIdx.x;   // 65536
    int k  = t >> 6;
    int c4 = t & 63;
    float4 v = ((const float4*)emb)[(size_t)k * 64 + c4];
    __nv_bfloat16 h0, h1, h2, h3, l0, l1, l2, l3;
    split2(v.x, h0, l0); split2(v.y, h1, l1);
    split2(v.z, h2, l2); split2(v.w, h3, l3);
    uint2 uh; uh.x = pack2(h0, h1); uh.y = pack2(h2, h3);
    uint2 ul; ul.x = pack2(l0, l1); ul.y = pack2(l2, l3);
    *(uint2*)((char*)g_eh + (size_t)k * 512 + c4 * 8) = uh;
    *(uint2*)((char*)g_el + (size_t)k * 512 + c4 * 8) = ul;
}

// ---------------------------------------------------------------------------
// Kernel 2: mma.sync split-bf16 GEMM + argmin(min1,min2) + ambiguity flag
// ---------------------------------------------------------------------------
__global__ void __launch_bounds__(256, 1)
vq_main_kernel(const float* __restrict__ lat) {
    extern __shared__ char sm[];
    const uint32_t sb = smem_u32(sm);

    const int tid  = threadIdx.x;
    const int wid  = tid >> 5;
    const int lane = tid & 31;
    const int g    = lane >> 2;
    const int tig  = lane & 3;
    const int r0   = blockIdx.x * BM;

    float* sNE = (float*)(sm + OFF_NE);
    float* sNX = (float*)(sm + OFF_NX);

    for (int t = tid; t < KCODES; t += 256) sNE[t] = g_norm_e[t];
    if (tid < BM) sNX[tid] = g_norm_x[r0 + tid];

    const float4* lat4 = (const float4*)lat;
    for (int t = tid; t < BM * 64; t += 256) {
        int row = t >> 6, c4 = t & 63;
        float4 v = lat4[(size_t)(r0 + row) * 64 + c4];
        __nv_bfloat16 h0, h1, h2, h3, l0, l1, l2, l3;
        split2(v.x, h0, l0); split2(v.y, h1, l1);
        split2(v.z, h2, l2); split2(v.w, h3, l3);
        uint2 uh; uh.x = pack2(h0, h1); uh.y = pack2(h2, h3);
        uint2 ul; ul.x = pack2(l0, l1); ul.y = pack2(l2, l3);
        *(uint2*)(sm + OFF_XH + row * XPITCH + c4 * 8) = uh;
        *(uint2*)(sm + OFF_XL + row * XPITCH + c4 * 8) = ul;
    }
    __syncthreads();

    const uint32_t a_off = (uint32_t)(16 * wid + (lane & 15)) * XPITCH + (lane >> 4) * 16;
    const uint32_t ah_base = sb + OFF_XH + a_off;
    const uint32_t al_base = sb + OFF_XL + a_off;
    const uint32_t b_off = (uint32_t)((lane & 7) + ((lane >> 4) & 1) * 8) * EPITCH
                         + ((lane >> 3) & 1) * 16;
    const uint32_t bh_base = sb + OFF_EH + b_off;
    const uint32_t bl_base = sb + OFF_EL + b_off;

    const int r_lo = 16 * wid + g;
    const int r_hi = r_lo + 8;
    const float nx_lo = sNX[r_lo];
    const float nx_hi = sNX[r_hi];

    float bv_lo = POS_INF, bv_hi = POS_INF, b2_lo = POS_INF, b2_hi = POS_INF;
    int   bi_lo = 0,       bi_hi = 0;

    for (int cc = 0; cc < NCHUNK; cc++) {
        float acc[16][4];
        #pragma unroll
        for (int n = 0; n < 16; n++)
            #pragma unroll
            for (int q = 0; q < 4; q++) acc[n][q] = 0.0f;

        for (int p = 0; p < NPANEL; p++) {
            __syncthreads();
            {
                const char* srcH = (const char*)g_eh + ((size_t)cc * 128) * 512 + p * 128;
                const char* srcL = (const char*)g_el + ((size_t)cc * 128) * 512 + p * 128;
                #pragma unroll
                for (int t = tid; t < 1024; t += 256) {
                    int r = t >> 3, c16 = t & 7;
                    *(uint4*)(sm + OFF_EH + r * EPITCH + c16 * 16) =
                        *(const uint4*)(srcH + (size_t)r * 512 + c16 * 16);
                    *(uint4*)(sm + OFF_EL + r * EPITCH + c16 * 16) =
                        *(const uint4*)(srcL + (size_t)r * 512 + c16 * 16);
                }
            }
            __syncthreads();

            #pragma unroll
            for (int kk = 0; kk < 4; kk++) {
                const int ks = p * 4 + kk;
                uint32_t ah0, ah1, ah2, ah3, al0, al1, al2, al3;
                ldm_x4(ah0, ah1, ah2, ah3, ah_base + ks * 32);
                ldm_x4(al0, al1, al2, al3, al_base + ks * 32);
                #pragma unroll
                for (int np = 0; np < 8; np++) {
                    uint32_t bh0, bh1, bh2, bh3, bl0, bl1, bl2, bl3;
                    ldm_x4(bh0, bh1, bh2, bh3, bh_base + np * (16 * EPITCH) + kk * 32);
                    ldm_x4(bl0, bl1, bl2, bl3, bl_base + np * (16 * EPITCH) + kk * 32);
                    mma16816(acc[2 * np],     ah0, ah1, ah2, ah3, bh0, bh1);
                    mma16816(acc[2 * np],     al0, al1, al2, al3, bh0, bh1);
                    mma16816(acc[2 * np],     ah0, ah1, ah2, ah3, bl0, bl1);
                    mma16816(acc[2 * np + 1], ah0, ah1, ah2, ah3, bh2, bh3);
                    mma16816(acc[2 * np + 1], al0, al1, al2, al3, bh2, bh3);
                    mma16816(acc[2 * np + 1], ah0, ah1, ah2, ah3, bl2, bl3);
                }
            }
        }

        const float* nep = sNE + cc * 128;
        #pragma unroll
        for (int nt = 0; nt < 16; nt++) {
            int c0   = nt * 8 + 2 * tig;
            int col0 = cc * 128 + c0;
            float ne0 = nep[c0], ne1 = nep[c0 + 1];
            float s;
            s = __fsub_rn(__fadd_rn(nx_lo, ne0), __fmul_rn(2.0f, acc[nt][0]));
            if (s < bv_lo) { b2_lo = bv_lo; bv_lo = s; bi_lo = col0; }
            else if (s < b2_lo) b2_lo = s;
            s = __fsub_rn(__fadd_rn(nx_lo, ne1), __fmul_rn(2.0f, acc[nt][1]));
            if (s < bv_lo) { b2_lo = bv_lo; bv_lo = s; bi_lo = col0 + 1; }
            else if (s < b2_lo) b2_lo = s;
            s = __fsub_rn(__fadd_rn(nx_hi, ne0), __fmul_rn(2.0f, acc[nt][2]));
            if (s < bv_hi) { b2_hi = bv_hi; bv_hi = s; bi_hi = col0; }
            else if (s < b2_hi) b2_hi = s;
            s = __fsub_rn(__fadd_rn(nx_hi, ne1), __fmul_rn(2.0f, acc[nt][3]));
            if (s < bv_hi) { b2_hi = bv_hi; bv_hi = s; bi_hi = col0 + 1; }
            else if (s < b2_hi) b2_hi = s;
        }
    }

    // reduce across quad (lex (val, idx); min2 via min(max(bv,ov), min(b2,ob2)))
    #pragma unroll
    for (int off = 1; off <= 2; off <<= 1) {
        float ov, ob2; int oi;
        ov  = __shfl_xor_sync(0xffffffffu, bv_lo, off);
        oi  = __shfl_xor_sync(0xffffffffu, bi_lo, off);
        ob2 = __shfl_xor_sync(0xffffffffu, b2_lo, off);
        b2_lo = fminf(fmaxf(bv_lo, ov), fminf(b2_lo, ob2));
        if (ov < bv_lo || (ov == bv_lo && oi < bi_lo)) { bv_lo = ov; bi_lo = oi; }
        ov  = __shfl_xor_sync(0xffffffffu, bv_hi, off);
        oi  = __shfl_xor_sync(0xffffffffu, bi_hi, off);
        ob2 = __shfl_xor_sync(0xffffffffu, b2_hi, off);
        b2_hi = fminf(fmaxf(bv_hi, ov), fminf(b2_hi, ob2));
        if (ov < bv_hi || (ov == bv_hi && oi < bi_hi)) { bv_hi = ov; bi_hi = oi; }
    }
    if (tig == 0) {
        g_idx[r0 + r_lo] = bi_lo;
        g_idx[r0 + r_hi] = bi_hi;
        if (b2_lo - bv_lo <= FLAG_EPS) {
            int slot = atomicAdd(&g_nflag, 1);
            g_flaglist[slot] = r0 + r_lo;
        }
        if (b2_hi - bv_hi <= FLAG_EPS) {
            int slot = atomicAdd(&g_nflag, 1);
            g_flaglist[slot] = r0 + r_hi;
        }
    }
}

// ---------------------------------------------------------------------------
// Kernel 2b: exact rescue for ambiguous rows (R5's exact op sequence)
// ---------------------------------------------------------------------------
__global__ void __launch_bounds__(256)
vq_rescue_kernel(const float* __restrict__ lat, const float* __restrict__ emb) {
    __shared__ float sX[8][DIM];
    const int tid  = threadIdx.x;
    const int wid  = tid >> 5;
    const int lane = tid & 31;
    const int nflag = g_nflag;
    const int gwarp = blockIdx.x * 8 + wid;

    for (int item = gwarp; item < nflag; item += 512 * 8) {
        const int row = g_flaglist[item];
        // load x row into smem
        const float4* x4 = (const float4*)(lat + (size_t)row * DIM);
        #pragma unroll
        for (int q = 0; q < 2; q++)
            ((float4*)sX[wid])[lane + 32 * q] = x4[lane + 32 * q];
        __syncwarp();

        const float nx = g_norm_x[row];
        float bv = POS_INF;
        int   bi = 0;
        const int cbase = lane * 32;
        for (int c = 0; c < 32; c++) {
            int code = cbase + c;
            const float4* e4 = (const float4*)(emb + (size_t)code * DIM);
            const float4* xs = (const float4*)sX[wid];
            float master = 0.0f;
            #pragma unroll
            for (int p = 0; p < 8; p++) {        // panels of 32 (R5 order)
                float acc = 0.0f;
                #pragma unroll
                for (int q = 0; q < 8; q++) {
                    float4 e = e4[p * 8 + q];
                    float4 x = xs[p * 8 + q];
                    acc = __fmaf_rn(x.x, e.x, acc);
                    acc = __fmaf_rn(x.y, e.y, acc);
                    acc = __fmaf_rn(x.z, e.z, acc);
                    acc = __fmaf_rn(x.w, e.w, acc);
                }
                master = __fadd_rn(master, acc);
            }
            float s = __fsub_rn(__fadd_rn(nx, g_norm_e[code]),
                                __fmul_rn(2.0f, master));
            if (s < bv) { bv = s; bi = code; }   // ascending -> first-min
        }
        // lex merge over 32 lanes
        #pragma unroll
        for (int off = 16; off >= 1; off >>= 1) {
            float ov = __shfl_xor_sync(0xffffffffu, bv, off);
            int   oi = __shfl_xor_sync(0xffffffffu, bi, off);
            if (ov < bv || (ov == bv && oi < bi)) { bv = ov; bi = oi; }
        }
        if (lane == 0) g_idx[row] = bi;
        __syncwarp();
    }
}

// ---------------------------------------------------------------------------
// Kernel 2c: epilogue — gather + output + per-block loss (R5 math)
// ---------------------------------------------------------------------------
__global__ void __launch_bounds__(256)
vq_epilogue_kernel(const float* __restrict__ lat, const float* __restrict__ emb,
                   float* __restrict__ out) {
    __shared__ int   sIdx[BM];
    __shared__ float sWS[8];
    const int tid = threadIdx.x;
    const int r0  = blockIdx.x * BM;
    if (tid < BM) sIdx[tid] = g_idx[r0 + tid];
    __syncthreads();

    float lsum = 0.0f;
    const float4* lat4 = (const float4*)lat;
    const float4* emb4 = (const float4*)emb;
    float4*       out4 = (float4*)out;
    for (int t = tid; t < BM * (DIM / 4); t += 256) {
        int row = t >> 6;
        int q   = t & 63;
        int code = sIdx[row];
        float4 e = emb4[(size_t)code * (DIM / 4) + q];
        float4 x = lat4[(size_t)(r0 + row) * (DIM / 4) + q];
        out4[(size_t)(r0 + row) * (DIM / 4) + q] = e;
        float dx = x.x - e.x, dy = x.y - e.y, dz = x.z - e.z, dw = x.w - e.w;
        lsum += dx * dx + dy * dy + dz * dz + dw * dw;
    }
    #pragma unroll
    for (int off = 16; off >= 1; off >>= 1)
        lsum += __shfl_xor_sync(0xffffffffu, lsum, off);
    if ((tid & 31) == 0) sWS[tid >> 5] = lsum;
    __syncthreads();
    if (tid == 0) {
        float tot = 0.0f;
        #pragma unroll
        for (int w = 0; w < 8; w++) tot += sWS[w];
        g_partial[blockIdx.x] = tot;
    }
}

// ---------------------------------------------------------------------------
// Kernel 3: deterministic loss finalize (unchanged)
// ---------------------------------------------------------------------------
__global__ void vq_finalize_kernel(float* __restrict__ out, int out_size) {
    __shared__ float s_warp[16];
    int tid = threadIdx.x;
    float v = g_partial[tid];
    #pragma unroll
    for (int off = 16; off >= 1; off >>= 1)
        v += __shfl_xor_sync(0xffffffffu, v, off);
    if ((tid & 31) == 0) s_warp[tid >> 5] = v;
    __syncthreads();
    if (tid == 0) {
        float tot = 0.0f;
        #pragma unroll
        for (int w = 0; w < 16; w++) tot += s_warp[w];
        float mse = tot / (float)((size_t)N_ROWS * DIM);
        float vq_loss = mse * 1.25f;
        if (out_size > N_ROWS * DIM) out[N_ROWS * DIM] = vq_loss;
    }
}

// ---------------------------------------------------------------------------
extern "C" void kernel_launch(void* const* d_in, const int* in_sizes, int n_in,
                              void* d_out, int out_size) {
    const float* lat = (const float*)d_in[0];
    const float* emb = (const float*)d_in[1];
    float* out = (float*)d_out;

    cudaFuncSetAttribute(vq_main_kernel,
                         cudaFuncAttributeMaxDynamicSharedMemorySize, SMEM_BYTES);

    vq_norms_e_kernel<<<(KCODES + 255) / 256, 256>>>(emb);
    vq_norms_x_kernel<<<(N_ROWS * 32 + 255) / 256, 256>>>(lat);
    vq_convert_e_kernel<<<256, 256>>>(emb);
    vq_main_kernel<<<NBLOCKS, 256, SMEM_BYTES>>>(lat);
    vq_rescue_kernel<<<512, 256>>>(lat, emb);
    vq_epilogue_kernel<<<NBLOCKS, 256>>>(lat, emb, out);
    vq_finalize_kernel<<<1, NBLOCKS>>>(out, out_size);
}